// round 1
// baseline (speedup 1.0000x reference)
#include <cuda_runtime.h>
#include <cuda_bf16.h>
#include <math.h>

// Scratch: per-batch-element partial (pos + neg_val). Max B we support.
#define MAX_B 32768
__device__ float g_partial[MAX_B];

__device__ __forceinline__ float log_sigmoid(float x) {
    // stable: logsig(x) = min(x,0) - log1p(exp(-|x|))
    return fminf(x, 0.0f) - log1pf(__expf(-fabsf(x)));
}

// One CTA per batch element; 128 threads = one per embedding dim.
__global__ void __launch_bounds__(128, 16)
skipgram_main(const int* __restrict__ target,
              const int* __restrict__ context,
              const int* __restrict__ neg,
              const float* __restrict__ emb,
              int B, int K)
{
    const int b = blockIdx.x;
    if (b >= B) return;
    const int d = threadIdx.x;           // 0..127
    const int lane = d & 31;
    const int wid  = d >> 5;             // 0..3

    __shared__ int s_neg[32];
    __shared__ float s_red[8];           // 4 warps x 2 values

    // Indices (broadcast loads — all threads same address, cheap)
    const int t = target[b];
    const int c = context[b];
    if (d < K) s_neg[d] = neg[b * K + d];
    __syncthreads();

    const float v = __ldg(&emb[(long long)t * 128 + d]);
    const float u = __ldg(&emb[(long long)c * 128 + d]);

    // Sum of negative rows (element-wise), then single dot with v.
    float s = 0.0f;
    #pragma unroll
    for (int k = 0; k < 20; ++k) {
        // K is 20 for this problem; guard for safety without killing unroll
        if (k < K) {
            long long row = (long long)s_neg[k] * 128;
            s += __ldg(&emb[row + d]);
        }
    }

    float pos_p = u * v;     // contribution to dot(u, v)
    float neg_p = s * v;     // contribution to dot(sum_neg, v)

    // Reduce both across 128 threads: warp shuffle, then smem across 4 warps.
    #pragma unroll
    for (int off = 16; off > 0; off >>= 1) {
        pos_p += __shfl_down_sync(0xffffffffu, pos_p, off);
        neg_p += __shfl_down_sync(0xffffffffu, neg_p, off);
    }
    if (lane == 0) {
        s_red[wid]     = pos_p;
        s_red[wid + 4] = neg_p;
    }
    __syncthreads();

    if (d == 0) {
        float dot_uv = s_red[0] + s_red[1] + s_red[2] + s_red[3];
        float dot_sv = s_red[4] + s_red[5] + s_red[6] + s_red[7];
        float pos     = log_sigmoid(dot_uv);
        float neg_val = log_sigmoid(-dot_sv);
        g_partial[b] = pos + neg_val;
    }
}

// Deterministic single-block reduction: out = -mean(g_partial[0..B))
__global__ void __launch_bounds__(1024, 1)
skipgram_reduce(float* __restrict__ out, int B)
{
    const int tid = threadIdx.x;
    __shared__ float s_red[32];

    float acc = 0.0f;
    for (int i = tid; i < B; i += 1024)
        acc += g_partial[i];

    // warp reduce
    #pragma unroll
    for (int off = 16; off > 0; off >>= 1)
        acc += __shfl_down_sync(0xffffffffu, acc, off);
    if ((tid & 31) == 0) s_red[tid >> 5] = acc;
    __syncthreads();

    if (tid < 32) {
        float w = (tid < 32) ? s_red[tid] : 0.0f;  // 1024/32 = 32 warps
        #pragma unroll
        for (int off = 16; off > 0; off >>= 1)
            w += __shfl_down_sync(0xffffffffu, w, off);
        if (tid == 0)
            out[0] = -w / (float)B;
    }
}

extern "C" void kernel_launch(void* const* d_in, const int* in_sizes, int n_in,
                              void* d_out, int out_size)
{
    const int*   target  = (const int*)d_in[0];
    const int*   context = (const int*)d_in[1];
    const int*   neg     = (const int*)d_in[2];
    const float* emb     = (const float*)d_in[3];
    float*       out     = (float*)d_out;

    const int B = in_sizes[0];
    const int K = in_sizes[2] / B;   // 20

    skipgram_main<<<B, 128>>>(target, context, neg, emb, B, K);
    skipgram_reduce<<<1, 1024>>>(out, B);
}

// round 2
// speedup vs baseline: 1.0009x; 1.0009x over previous
#include <cuda_runtime.h>
#include <cuda_bf16.h>
#include <math.h>

#define WARPS_PER_BLOCK 8
#define MAX_BLOCKS 8192

__device__ float        g_partial[MAX_BLOCKS];
__device__ unsigned int g_count;   // starts 0 (static init); atomicInc auto-wraps to 0 each run

__device__ __forceinline__ float log_sigmoid(float x) {
    // stable: logsig(x) = min(x,0) - log1p(exp(-|x|))
    return fminf(x, 0.0f) - log1pf(__expf(-fabsf(x)));
}

// One warp per batch element, float4 (16B) loads: each warp-load covers a full
// 512B embedding row. Last block to finish reduces all block partials
// deterministically (fixed order) and writes -mean.
__global__ void __launch_bounds__(256, 8)
skipgram_fused(const int* __restrict__ target,
               const int* __restrict__ context,
               const int* __restrict__ neg,
               const float4* __restrict__ emb4,
               float* __restrict__ out,
               int B, int K, int nblocks)
{
    const int lane = threadIdx.x & 31;
    const int wid  = threadIdx.x >> 5;
    const int b    = blockIdx.x * WARPS_PER_BLOCK + wid;

    __shared__ float s_red[WARPS_PER_BLOCK];
    __shared__ int   s_last;

    float result = 0.0f;
    if (b < B) {
        // per-warp scalar indices (broadcast loads)
        const int t = target[b];
        const int c = context[b];
        // lanes 0..K-1 hold the negative indices; broadcast via shfl in the loop
        int my_neg = (lane < K) ? neg[b * K + lane] : 0;

        float4 v = __ldg(&emb4[(long long)t * 32 + lane]);
        float4 u = __ldg(&emb4[(long long)c * 32 + lane]);

        // Sum of the 20 negative rows element-wise (algebraic fusion:
        // sum_k dot(u_k, v) == dot(sum_k u_k, v)), then one dot at the end.
        float4 s = make_float4(0.f, 0.f, 0.f, 0.f);
        #pragma unroll
        for (int k = 0; k < 20; ++k) {
            if (k < K) {
                int idx = __shfl_sync(0xffffffffu, my_neg, k);
                float4 r = __ldg(&emb4[(long long)idx * 32 + lane]);
                s.x += r.x; s.y += r.y; s.z += r.z; s.w += r.w;
            }
        }

        float pos_p = u.x * v.x + u.y * v.y + u.z * v.z + u.w * v.w;
        float neg_p = s.x * v.x + s.y * v.y + s.z * v.z + s.w * v.w;

        #pragma unroll
        for (int off = 16; off > 0; off >>= 1) {
            pos_p += __shfl_down_sync(0xffffffffu, pos_p, off);
            neg_p += __shfl_down_sync(0xffffffffu, neg_p, off);
        }
        if (lane == 0)
            result = log_sigmoid(pos_p) + log_sigmoid(-neg_p);
    }

    if (lane == 0) s_red[wid] = result;
    __syncthreads();

    // Block partial (fixed intra-block order), then last-arriving block reduces.
    if (threadIdx.x == 0) {
        float acc = 0.0f;
        #pragma unroll
        for (int w = 0; w < WARPS_PER_BLOCK; ++w) acc += s_red[w];
        g_partial[blockIdx.x] = acc;
        __threadfence();
        unsigned prev = atomicInc(&g_count, (unsigned)(nblocks - 1)); // wraps to 0
        s_last = (prev == (unsigned)(nblocks - 1)) ? 1 : 0;
    }
    __syncthreads();

    if (s_last) {
        __threadfence();
        // Deterministic final reduction over nblocks partials by the 256 threads.
        float acc = 0.0f;
        for (int i = threadIdx.x; i < nblocks; i += 256)
            acc += g_partial[i];
        #pragma unroll
        for (int off = 16; off > 0; off >>= 1)
            acc += __shfl_down_sync(0xffffffffu, acc, off);
        if (lane == 0) s_red[wid] = acc;
        __syncthreads();
        if (threadIdx.x == 0) {
            float tot = 0.0f;
            #pragma unroll
            for (int w = 0; w < WARPS_PER_BLOCK; ++w) tot += s_red[w];
            out[0] = -tot / (float)B;
        }
    }
}

extern "C" void kernel_launch(void* const* d_in, const int* in_sizes, int n_in,
                              void* d_out, int out_size)
{
    const int*    target  = (const int*)d_in[0];
    const int*    context = (const int*)d_in[1];
    const int*    neg     = (const int*)d_in[2];
    const float4* emb4    = (const float4*)d_in[3];
    float*        out     = (float*)d_out;

    const int B = in_sizes[0];
    const int K = in_sizes[2] / B;   // 20
    const int nblocks = (B + WARPS_PER_BLOCK - 1) / WARPS_PER_BLOCK;  // 2048

    skipgram_fused<<<nblocks, 256>>>(target, context, neg, emb4, out, B, K, nblocks);
}